// round 6
// baseline (speedup 1.0000x reference)
#include <cuda_runtime.h>
#include <mma.h>
#include <math.h>
#include <stdint.h>

using namespace nvcuda;

#define N_NODES   100000
#define DEG       16
#define IN_DIM    128
#define OUT_DIM   32
#define EPS       1e-8f

// scratch (device globals: no allocation allowed in kernel_launch)
__device__ float g_z[N_NODES * OUT_DIM];
__device__ float g_inorm[N_NODES];              // 1 / max(||z_i||, EPS)
__device__ float g_Wtf[OUT_DIM * IN_DIM];       // tf32-rounded W

__device__ __forceinline__ float f2tf32(float x) {
    float r;
    asm("cvt.rna.tf32.f32 %0, %1;" : "=f"(r) : "f"(x));
    return r;
}

// ---------------------------------------------------------------------------
// Kernel 0: round W to tf32 once (4096 elements).
// ---------------------------------------------------------------------------
__global__ void prep_w_kernel(const float* __restrict__ W)
{
    int i = blockIdx.x * blockDim.x + threadIdx.x;
    if (i < OUT_DIM * IN_DIM) g_Wtf[i] = f2tf32(W[i]);
}

// ---------------------------------------------------------------------------
// Kernel 1: z = h @ W^T via wmma TF32 (m16n16k8), fused inverse row norms.
// NON-persistent: one CTA per 64-row tile (1563 CTAs), 128 threads = 4 warps.
// Latency hidden by CTA-level overlap (~4 CTAs/SM).
// Warp w: rows (w&1)*32..+32 (two m16 tiles), cols (w>>1)*16 (one n16 tile).
// B fragments load DIRECTLY from gmem (g_Wtf, 16KB, L1-resident).
// Static smem: hs [64][132] (33792B) + zsm [64][36] (9216B) = 43008B.
// ---------------------------------------------------------------------------
#define LDH 132
#define LDZ 36

__global__ __launch_bounds__(128) void gemm_wmma_kernel(
    const float* __restrict__ h, int N)
{
    __shared__ float hs[64 * LDH];
    __shared__ float zsm[64 * LDZ];

    const int tid  = threadIdx.x;
    const int wid  = tid >> 5;
    const int m0w  = (wid & 1) * 32;
    const int n0   = (wid >> 1) * 16;
    const int row0 = blockIdx.x * 64;
    const unsigned FULL = 0xffffffffu;

    // ---- preload all 16 B fragments straight from gmem (col-major view) ----
    wmma::fragment<wmma::matrix_b, 16, 16, 8, wmma::precision::tf32,
                   wmma::col_major> bfr[16];
    #pragma unroll
    for (int ks = 0; ks < 16; ks++)
        wmma::load_matrix_sync(bfr[ks], &g_Wtf[n0 * IN_DIM + ks * 8], IN_DIM);

    // ---- load 64-row h tile -> tf32-rounded smem ----
    const float4* h4 = reinterpret_cast<const float4*>(h);
    #pragma unroll
    for (int i = 0; i < 16; i++) {
        int f    = tid + i * 128;          // float4 index 0..2047
        int r    = f >> 5;                 // 0..63
        int k4   = f & 31;                 // 0..31
        int grow = row0 + r;
        if (grow >= N) grow = N - 1;
        float4 v = __ldg(&h4[grow * 32 + k4]);
        float* d = &hs[r * LDH + k4 * 4];
        d[0] = f2tf32(v.x); d[1] = f2tf32(v.y);
        d[2] = f2tf32(v.z); d[3] = f2tf32(v.w);
    }
    __syncthreads();

    // ---- wmma: 2 m-tiles x 16 k-steps ----
    wmma::fragment<wmma::accumulator, 16, 16, 8, float> c0, c1;
    wmma::fill_fragment(c0, 0.0f);
    wmma::fill_fragment(c1, 0.0f);
    wmma::fragment<wmma::matrix_a, 16, 16, 8, wmma::precision::tf32,
                   wmma::row_major> a0, a1;
    #pragma unroll
    for (int ks = 0; ks < 16; ks++) {
        wmma::load_matrix_sync(a0, &hs[m0w * LDH + ks * 8], LDH);
        wmma::load_matrix_sync(a1, &hs[(m0w + 16) * LDH + ks * 8], LDH);
        wmma::mma_sync(c0, a0, bfr[ks], c0);
        wmma::mma_sync(c1, a1, bfr[ks], c1);
    }
    wmma::store_matrix_sync(&zsm[m0w * LDZ + n0], c0, LDZ, wmma::mem_row_major);
    wmma::store_matrix_sync(&zsm[(m0w + 16) * LDZ + n0], c1, LDZ, wmma::mem_row_major);
    __syncthreads();

    // ---- epilogue: coalesced z write + inverse norms ----
    int row  = tid >> 1;
    int colh = (tid & 1) * 16;
    float4 z4[4];
    float ss = 0.f;
    #pragma unroll
    for (int i = 0; i < 4; i++) {
        z4[i] = *reinterpret_cast<const float4*>(&zsm[row * LDZ + colh + i * 4]);
        ss += z4[i].x * z4[i].x + z4[i].y * z4[i].y
            + z4[i].z * z4[i].z + z4[i].w * z4[i].w;
    }
    ss += __shfl_xor_sync(FULL, ss, 1);
    int grow = row0 + row;
    if (grow < N) {
        float4* dst = reinterpret_cast<float4*>(&g_z[grow * OUT_DIM + colh]);
        #pragma unroll
        for (int i = 0; i < 4; i++) dst[i] = z4[i];
        if ((tid & 1) == 0)
            g_inorm[grow] = 1.0f / fmaxf(sqrtf(ss), EPS);
    }
}

// ---------------------------------------------------------------------------
// Kernel 2: per-node cosine attention + softmax + weighted aggregation.
// Half-warp per node; hierarchical multi-reduce (30 shfl/warp for 32 dots).
// exp simplified: exp(-beta(1-cos)) -> exp(beta*cos), constant cancels.
// __launch_bounds__(256,5) to push regs <= 51 -> 40 warps/SM.
// ---------------------------------------------------------------------------
__global__ __launch_bounds__(256, 5) void edge_agg_kernel(
    const float* __restrict__ beta_p, const int* __restrict__ src,
    float* __restrict__ out, int N)
{
    __shared__ float alpha_sm[8][32];

    const int warp_id = (blockIdx.x * blockDim.x + threadIdx.x) >> 5;
    if (warp_id * 2 >= N) return;

    const int w    = threadIdx.x >> 5;
    const int lane = threadIdx.x & 31;
    const int half = lane >> 4;
    const int hl   = lane & 15;
    int node = warp_id * 2 + half;
    const bool valid = (node < N);
    if (!valid) node = N - 1;

    const unsigned FULL = 0xffffffffu;
    const float beta = __ldg(beta_p);

    const float2 zd    = *reinterpret_cast<const float2*>(&g_z[node * OUT_DIM + 2 * hl]);
    const float inv_nd = g_inorm[node];

    const int4* sp = reinterpret_cast<const int4*>(src + node * DEG);
    int4 s0 = __ldg(sp + 0);
    int4 s1 = __ldg(sp + 1);
    int4 s2 = __ldg(sp + 2);
    int4 s3 = __ldg(sp + 3);
    int si[DEG] = { s0.x, s0.y, s0.z, s0.w,  s1.x, s1.y, s1.z, s1.w,
                    s2.x, s2.y, s2.z, s2.w,  s3.x, s3.y, s3.z, s3.w };

    // own-edge src (coalesced) -> per-edge cosine scale
    const int sid_own = __ldg(src + node * DEG + hl);
    const float cc = __ldg(&g_inorm[sid_own]) * inv_nd;

    // 4-bit bit-reversal (involution): lane hl ends holding edge hl's dot
    constexpr int REV4[16] = {0,8,4,12, 2,10,6,14, 1,9,5,13, 3,11,7,15};

    float2 v[DEG];
    #pragma unroll
    for (int k = 0; k < DEG; k++)
        v[k] = *reinterpret_cast<const float2*>(&g_z[si[REV4[k]] * OUT_DIM + 2 * hl]);

    float p[DEG];
    #pragma unroll
    for (int k = 0; k < DEG; k++)
        p[k] = fmaf(v[k].x, zd.x, v[k].y * zd.y);

    const bool b8 = (hl & 8) != 0;
    const bool b4 = (hl & 4) != 0;
    const bool b2 = (hl & 2) != 0;
    const bool b1 = (hl & 1) != 0;

    float s[8];
    #pragma unroll
    for (int i = 0; i < 8; i++) {
        float a = p[2 * i]     + __shfl_xor_sync(FULL, p[2 * i], 8);
        float b = p[2 * i + 1] + __shfl_xor_sync(FULL, p[2 * i + 1], 8);
        s[i] = b8 ? b : a;
    }
    float q[4];
    #pragma unroll
    for (int i = 0; i < 4; i++) {
        float a = s[2 * i]     + __shfl_xor_sync(FULL, s[2 * i], 4);
        float b = s[2 * i + 1] + __shfl_xor_sync(FULL, s[2 * i + 1], 4);
        q[i] = b4 ? b : a;
    }
    float w2_[2];
    #pragma unroll
    for (int i = 0; i < 2; i++) {
        float a = q[2 * i]     + __shfl_xor_sync(FULL, q[2 * i], 2);
        float b = q[2 * i + 1] + __shfl_xor_sync(FULL, q[2 * i + 1], 2);
        w2_[i] = b2 ? b : a;
    }
    float xa = w2_[0] + __shfl_xor_sync(FULL, w2_[0], 1);
    float xb = w2_[1] + __shfl_xor_sync(FULL, w2_[1], 1);
    float dotv = b1 ? xb : xa;                 // raw dot of edge `hl`

    // softmax weight: exp(-beta(1-cos)) -> exp(beta*cos) (constant cancels);
    // beta in [0,1), cos <= 1 -> no overflow, no max subtraction needed.
    float esc = __expf(beta * (dotv * cc));

    float denom = esc;
    denom += __shfl_xor_sync(FULL, denom, 8);
    denom += __shfl_xor_sync(FULL, denom, 4);
    denom += __shfl_xor_sync(FULL, denom, 2);
    denom += __shfl_xor_sync(FULL, denom, 1);

    // publish esc in REV4-permuted order: slot j holds esc of edge REV4[j]
    alpha_sm[w][(lane & 16) | REV4[hl]] = esc;
    __syncwarp(FULL);

    const float4* ap = reinterpret_cast<const float4*>(&alpha_sm[w][lane & 16]);
    float ox = 0.f, oy = 0.f;
    #pragma unroll
    for (int k4 = 0; k4 < 4; k4++) {
        float4 a4 = ap[k4];
        ox = fmaf(a4.x, v[4 * k4 + 0].x, ox);
        oy = fmaf(a4.x, v[4 * k4 + 0].y, oy);
        ox = fmaf(a4.y, v[4 * k4 + 1].x, ox);
        oy = fmaf(a4.y, v[4 * k4 + 1].y, oy);
        ox = fmaf(a4.z, v[4 * k4 + 2].x, ox);
        oy = fmaf(a4.z, v[4 * k4 + 2].y, oy);
        ox = fmaf(a4.w, v[4 * k4 + 3].x, ox);
        oy = fmaf(a4.w, v[4 * k4 + 3].y, oy);
    }

    if (valid) {
        float invd = 1.0f / denom;
        *reinterpret_cast<float2*>(&out[node * OUT_DIM + 2 * hl]) =
            make_float2(ox * invd, oy * invd);
    }
}

extern "C" void kernel_launch(void* const* d_in, const int* in_sizes, int n_in,
                              void* d_out, int out_size)
{
    const float* h    = (const float*)d_in[0];   // [N, 128]
    const float* W    = (const float*)d_in[1];   // [32, 128]
    const float* beta = (const float*)d_in[2];   // [1]
    const int*   src  = (const int*)d_in[3];     // [E]
    float* out = (float*)d_out;

    int N = in_sizes[0] / IN_DIM;                // 100000
    int ntiles = (N + 63) / 64;                  // 1563

    prep_w_kernel<<<16, 256>>>(W);
    gemm_wmma_kernel<<<ntiles, 128>>>(h, N);

    int nwarps  = (N + 1) / 2;
    int nblocks = (nwarps + 7) / 8;              // 8 warps / block
    edge_agg_kernel<<<nblocks, 256>>>(beta, src, out, N);
}

// round 7
// speedup vs baseline: 1.1981x; 1.1981x over previous
#include <cuda_runtime.h>
#include <mma.h>
#include <math.h>
#include <stdint.h>

using namespace nvcuda;

#define N_NODES   100000
#define DEG       16
#define IN_DIM    128
#define OUT_DIM   32
#define EPS       1e-8f

// scratch (device globals: no allocation allowed in kernel_launch)
__device__ float g_z[N_NODES * OUT_DIM];
__device__ float g_inorm[N_NODES];          // 1 / max(||z_i||, EPS)

__device__ __forceinline__ float f2tf32(float x) {
    float r;
    asm("cvt.rna.tf32.f32 %0, %1;" : "=f"(r) : "f"(x));
    return r;
}

// ---------------------------------------------------------------------------
// Kernel 1: z = h @ W^T via wmma TF32 (m16n16k8), fused inverse row norms.
// NON-persistent: one CTA per 128-row tile (782 CTAs), 256 threads = 8 warps.
// 100.5KB dynamic smem -> 2 CTAs/SM = 16 warps/SM; latency hidden by
// CTA/warp-level overlap (independent CTAs), no persistent tail.
// Warp w: rows (w&3)*32..+32 (two m16 tiles), cols (w>>2)*16 (one n16 tile).
// W staged to smem (coalesced) once per CTA; 16 B fragments then preloaded
// into registers from smem.
// Dynamic smem (floats):
//   Ws  [32][132]  @ 0      (16896 B)
//   hs  [128][132] @ 4224   (67584 B)
//   zsm [128][36]  @ 21120  (18432 B)    total 102912 B
// ---------------------------------------------------------------------------
#define LDH 132
#define LDZ 36
#define GEMM_SMEM_BYTES 102912

__global__ __launch_bounds__(256) void gemm_wmma_kernel(
    const float* __restrict__ h, const float* __restrict__ W, int N)
{
    extern __shared__ float sm[];
    float* Ws  = sm;            // [32][132]
    float* hs  = sm + 4224;     // [128][132]
    float* zsm = sm + 21120;    // [128][36]

    const int tid  = threadIdx.x;
    const int wid  = tid >> 5;
    const int m0w  = (wid & 3) * 32;
    const int n0   = (wid >> 2) * 16;
    const int row0 = blockIdx.x * 128;
    const unsigned FULL = 0xffffffffu;

    // ---- stage W -> tf32-rounded smem (coalesced float4) ----
    const float4* W4 = reinterpret_cast<const float4*>(W);
    #pragma unroll
    for (int i = 0; i < 4; i++) {
        int f  = tid + i * 256;            // float4 index 0..1023
        int n  = f >> 5;
        int k4 = f & 31;
        float4 v = __ldg(&W4[n * 32 + k4]);
        float* d = &Ws[n * LDH + k4 * 4];
        d[0] = f2tf32(v.x); d[1] = f2tf32(v.y);
        d[2] = f2tf32(v.z); d[3] = f2tf32(v.w);
    }

    // ---- load 128-row h tile -> tf32-rounded smem ----
    const float4* h4 = reinterpret_cast<const float4*>(h);
    #pragma unroll
    for (int i = 0; i < 16; i++) {
        int f    = tid + i * 256;          // float4 index 0..4095
        int r    = f >> 5;                 // 0..127
        int k4   = f & 31;                 // 0..31
        int grow = row0 + r;
        if (grow >= N) grow = N - 1;
        float4 v = __ldg(&h4[grow * 32 + k4]);
        float* d = &hs[r * LDH + k4 * 4];
        d[0] = f2tf32(v.x); d[1] = f2tf32(v.y);
        d[2] = f2tf32(v.z); d[3] = f2tf32(v.w);
    }
    __syncthreads();

    // ---- preload all 16 B fragments from smem ----
    wmma::fragment<wmma::matrix_b, 16, 16, 8, wmma::precision::tf32,
                   wmma::col_major> bfr[16];
    #pragma unroll
    for (int ks = 0; ks < 16; ks++)
        wmma::load_matrix_sync(bfr[ks], &Ws[n0 * LDH + ks * 8], LDH);

    // ---- wmma: 2 m-tiles x 16 k-steps per warp ----
    wmma::fragment<wmma::accumulator, 16, 16, 8, float> c0, c1;
    wmma::fill_fragment(c0, 0.0f);
    wmma::fill_fragment(c1, 0.0f);
    wmma::fragment<wmma::matrix_a, 16, 16, 8, wmma::precision::tf32,
                   wmma::row_major> a0, a1;
    #pragma unroll
    for (int ks = 0; ks < 16; ks++) {
        wmma::load_matrix_sync(a0, &hs[m0w * LDH + ks * 8], LDH);
        wmma::load_matrix_sync(a1, &hs[(m0w + 16) * LDH + ks * 8], LDH);
        wmma::mma_sync(c0, a0, bfr[ks], c0);
        wmma::mma_sync(c1, a1, bfr[ks], c1);
    }
    wmma::store_matrix_sync(&zsm[m0w * LDZ + n0], c0, LDZ, wmma::mem_row_major);
    wmma::store_matrix_sync(&zsm[(m0w + 16) * LDZ + n0], c1, LDZ, wmma::mem_row_major);
    __syncthreads();

    // ---- epilogue: coalesced z write + inverse norms ----
    // thread t: row = t/2 (0..127), col half = (t&1)*16
    int row  = tid >> 1;
    int colh = (tid & 1) * 16;
    float4 z4[4];
    float ss = 0.f;
    #pragma unroll
    for (int i = 0; i < 4; i++) {
        z4[i] = *reinterpret_cast<const float4*>(&zsm[row * LDZ + colh + i * 4]);
        ss += z4[i].x * z4[i].x + z4[i].y * z4[i].y
            + z4[i].z * z4[i].z + z4[i].w * z4[i].w;
    }
    ss += __shfl_xor_sync(FULL, ss, 1);
    int grow = row0 + row;
    if (grow < N) {
        float4* dst = reinterpret_cast<float4*>(&g_z[grow * OUT_DIM + colh]);
        #pragma unroll
        for (int i = 0; i < 4; i++) dst[i] = z4[i];
        if ((tid & 1) == 0)
            g_inorm[grow] = 1.0f / fmaxf(sqrtf(ss), EPS);
    }
}

// ---------------------------------------------------------------------------
// Kernel 2: per-node cosine attention + softmax + weighted aggregation.
// Half-warp per node; hierarchical multi-reduce (30 shfl/warp for 32 dots).
// exp simplified: exp(-beta(1-cos)) -> exp(beta*cos), constant cancels.
// ---------------------------------------------------------------------------
__global__ __launch_bounds__(256) void edge_agg_kernel(
    const float* __restrict__ beta_p, const int* __restrict__ src,
    float* __restrict__ out, int N)
{
    __shared__ float alpha_sm[8][32];

    const int warp_id = (blockIdx.x * blockDim.x + threadIdx.x) >> 5;
    if (warp_id * 2 >= N) return;

    const int w    = threadIdx.x >> 5;
    const int lane = threadIdx.x & 31;
    const int half = lane >> 4;
    const int hl   = lane & 15;
    int node = warp_id * 2 + half;
    const bool valid = (node < N);
    if (!valid) node = N - 1;

    const unsigned FULL = 0xffffffffu;
    const float beta = __ldg(beta_p);

    const float2 zd    = *reinterpret_cast<const float2*>(&g_z[node * OUT_DIM + 2 * hl]);
    const float inv_nd = g_inorm[node];

    const int4* sp = reinterpret_cast<const int4*>(src + node * DEG);
    int4 s0 = __ldg(sp + 0);
    int4 s1 = __ldg(sp + 1);
    int4 s2 = __ldg(sp + 2);
    int4 s3 = __ldg(sp + 3);
    int si[DEG] = { s0.x, s0.y, s0.z, s0.w,  s1.x, s1.y, s1.z, s1.w,
                    s2.x, s2.y, s2.z, s2.w,  s3.x, s3.y, s3.z, s3.w };

    // own-edge src (coalesced) -> per-edge cosine scale
    const int sid_own = __ldg(src + node * DEG + hl);
    const float cc = __ldg(&g_inorm[sid_own]) * inv_nd;

    // 4-bit bit-reversal (involution): lane hl ends holding edge hl's dot
    constexpr int REV4[16] = {0,8,4,12, 2,10,6,14, 1,9,5,13, 3,11,7,15};

    float2 v[DEG];
    #pragma unroll
    for (int k = 0; k < DEG; k++)
        v[k] = *reinterpret_cast<const float2*>(&g_z[si[REV4[k]] * OUT_DIM + 2 * hl]);

    float p[DEG];
    #pragma unroll
    for (int k = 0; k < DEG; k++)
        p[k] = fmaf(v[k].x, zd.x, v[k].y * zd.y);

    const bool b8 = (hl & 8) != 0;
    const bool b4 = (hl & 4) != 0;
    const bool b2 = (hl & 2) != 0;
    const bool b1 = (hl & 1) != 0;

    float s[8];
    #pragma unroll
    for (int i = 0; i < 8; i++) {
        float a = p[2 * i]     + __shfl_xor_sync(FULL, p[2 * i], 8);
        float b = p[2 * i + 1] + __shfl_xor_sync(FULL, p[2 * i + 1], 8);
        s[i] = b8 ? b : a;
    }
    float q[4];
    #pragma unroll
    for (int i = 0; i < 4; i++) {
        float a = s[2 * i]     + __shfl_xor_sync(FULL, s[2 * i], 4);
        float b = s[2 * i + 1] + __shfl_xor_sync(FULL, s[2 * i + 1], 4);
        q[i] = b4 ? b : a;
    }
    float w2_[2];
    #pragma unroll
    for (int i = 0; i < 2; i++) {
        float a = q[2 * i]     + __shfl_xor_sync(FULL, q[2 * i], 2);
        float b = q[2 * i + 1] + __shfl_xor_sync(FULL, q[2 * i + 1], 2);
        w2_[i] = b2 ? b : a;
    }
    float xa = w2_[0] + __shfl_xor_sync(FULL, w2_[0], 1);
    float xb = w2_[1] + __shfl_xor_sync(FULL, w2_[1], 1);
    float dotv = b1 ? xb : xa;                 // raw dot of edge `hl`

    // softmax weight: exp(-beta(1-cos)) -> exp(beta*cos) (constant cancels);
    // beta in [0,1), cos <= 1 -> no overflow, no max subtraction needed.
    float esc = __expf(beta * (dotv * cc));

    float denom = esc;
    denom += __shfl_xor_sync(FULL, denom, 8);
    denom += __shfl_xor_sync(FULL, denom, 4);
    denom += __shfl_xor_sync(FULL, denom, 2);
    denom += __shfl_xor_sync(FULL, denom, 1);

    // publish esc in REV4-permuted order: slot j holds esc of edge REV4[j]
    alpha_sm[w][(lane & 16) | REV4[hl]] = esc;
    __syncwarp(FULL);

    const float4* ap = reinterpret_cast<const float4*>(&alpha_sm[w][lane & 16]);
    float ox = 0.f, oy = 0.f;
    #pragma unroll
    for (int k4 = 0; k4 < 4; k4++) {
        float4 a4 = ap[k4];
        ox = fmaf(a4.x, v[4 * k4 + 0].x, ox);
        oy = fmaf(a4.x, v[4 * k4 + 0].y, oy);
        ox = fmaf(a4.y, v[4 * k4 + 1].x, ox);
        oy = fmaf(a4.y, v[4 * k4 + 1].y, oy);
        ox = fmaf(a4.z, v[4 * k4 + 2].x, ox);
        oy = fmaf(a4.z, v[4 * k4 + 2].y, oy);
        ox = fmaf(a4.w, v[4 * k4 + 3].x, ox);
        oy = fmaf(a4.w, v[4 * k4 + 3].y, oy);
    }

    if (valid) {
        float invd = 1.0f / denom;
        *reinterpret_cast<float2*>(&out[node * OUT_DIM + 2 * hl]) =
            make_float2(ox * invd, oy * invd);
    }
}

extern "C" void kernel_launch(void* const* d_in, const int* in_sizes, int n_in,
                              void* d_out, int out_size)
{
    const float* h    = (const float*)d_in[0];   // [N, 128]
    const float* W    = (const float*)d_in[1];   // [32, 128]
    const float* beta = (const float*)d_in[2];   // [1]
    const int*   src  = (const int*)d_in[3];     // [E]
    float* out = (float*)d_out;

    int N = in_sizes[0] / IN_DIM;                // 100000
    int ntiles = (N + 127) / 128;                // 782

    cudaFuncSetAttribute(gemm_wmma_kernel,
                         cudaFuncAttributeMaxDynamicSharedMemorySize,
                         GEMM_SMEM_BYTES);
    gemm_wmma_kernel<<<ntiles, 256, GEMM_SMEM_BYTES>>>(h, W, N);

    int nwarps  = (N + 1) / 2;
    int nblocks = (nwarps + 7) / 8;              // 8 warps / block
    edge_agg_kernel<<<nblocks, 256>>>(beta, src, out, N);
}